// round 2
// baseline (speedup 1.0000x reference)
#include <cuda_runtime.h>
#include <math.h>

// ---------------- static problem config ----------------
constexpr int NN   = 100000;   // nodes
constexpr int EE   = 1600000;  // edges
constexpr int IND  = 128;      // input dim
constexpr int DD   = 64;       // hidden dim
constexpr int HH   = 16;       // heads
constexpr int GG   = 512;      // graphs
constexpr int HS   = 128;      // H*S
constexpr int FOUT = 384;      // 3*H*S
constexpr int PEN  = 128;
constexpr int CC   = 10;

// ---------------- device scratch (static: no allocations allowed) ----------------
__device__ float g_xh [NN * DD];    // sigmoid(x@fc_w^T+b)
__device__ float g_zx [NN * HS];    // xh @ Z0^T
__device__ float g_xs [NN * DD];    // cur * dinv (scatter source)
__device__ float g_agg[NN * DD];    // rwconv aggregate
__device__ float g_cur[NN * DD];    // rwconv output features
__device__ float g_dinv[NN];        // deg accumulator -> 1/(deg+1)
__device__ float g_Z1 [HS * DD];
__device__ float g_Z2 [HS * DD];
__device__ float g_tg [3 * GG * HS];   // per-step per-graph sums
__device__ float g_bna[FOUT];
__device__ float g_bnb[FOUT];

// triu_indices(8, 1) in numpy row-major order
__constant__ int c_iu[28] = {0,0,0,0,0,0,0, 1,1,1,1,1,1, 2,2,2,2,2, 3,3,3,3, 4,4,4, 5,5, 6};
__constant__ int c_ju[28] = {1,2,3,4,5,6,7, 2,3,4,5,6,7, 3,4,5,6,7, 4,5,6,7, 5,6,7, 6,7, 7};

// ---------------- small utility kernels ----------------
__global__ void k_zero() {
    int i = blockIdx.x * 256 + threadIdx.x;   // grid covers 3*GG*HS = 196608
    if (i < NN) g_dinv[i] = 0.f;
    if (i < 3 * GG * HS) g_tg[i] = 0.f;
}

__global__ void k_deg(const int* __restrict__ ei) {
    int e = blockIdx.x * 256 + threadIdx.x;
    if (e < EE) atomicAdd(&g_dinv[ei[e]], 1.0f);
}

__global__ void k_dinv() {
    int n = blockIdx.x * 256 + threadIdx.x;
    if (n < NN) g_dinv[n] = 1.0f / (g_dinv[n] + 1.0f);   // +1 self loop
}

// build A (symmetric relu'd upper-tri), Z1 = A@Z0, Z2 = A@Z1   (one block)
__global__ void k_prep(const float* __restrict__ adj, const float* __restrict__ Z0) {
    __shared__ float A[HH * 64];        // [h][i][j]
    __shared__ float Z1s[HS * DD];      // 32KB
    int t = threadIdx.x;                // 256 threads
    for (int p = t; p < HH * 64; p += 256) A[p] = 0.f;
    __syncthreads();
    for (int p = t; p < HH * 28; p += 256) {
        int h = p / 28, q = p % 28;
        float v = fmaxf(adj[h * 28 + q], 0.f);
        A[h * 64 + c_iu[q] * 8 + c_ju[q]] = v;
        A[h * 64 + c_ju[q] * 8 + c_iu[q]] = v;
    }
    __syncthreads();
    for (int p = t; p < HS * DD; p += 256) {
        int h = p >> 9, rem = p & 511, a = rem >> 6, d = rem & 63;
        float s = 0.f;
        #pragma unroll
        for (int b = 0; b < 8; ++b) s += A[h * 64 + a * 8 + b] * Z0[(h * 8 + b) * DD + d];
        Z1s[p] = s; g_Z1[p] = s;
    }
    __syncthreads();
    for (int p = t; p < HS * DD; p += 256) {
        int h = p >> 9, rem = p & 511, a = rem >> 6, d = rem & 63;
        float s = 0.f;
        #pragma unroll
        for (int b = 0; b < 8; ++b) s += A[h * 64 + a * 8 + b] * Z1s[(h * 8 + b) * DD + d];
        g_Z2[p] = s;
    }
}

// xs = src * dinv[n]; agg initialized to self-loop term (vectorized float4)
__global__ void k_scale(const float* __restrict__ src) {
    int i = blockIdx.x * 256 + threadIdx.x;   // i indexes float4, NN*16 total
    if (i >= NN * 16) return;
    int n = i >> 4;
    float dv = g_dinv[n];
    float4 v = ((const float4*)src)[i];
    v.x *= dv; v.y *= dv; v.z *= dv; v.w *= dv;
    ((float4*)g_xs)[i]  = v;
    ((float4*)g_agg)[i] = v;
}

// agg[col] += xs[row] via vector reductions (4 threads per edge, 16 floats each)
__global__ void k_scatter(const int* __restrict__ ei) {
    int idx = blockIdx.x * 256 + threadIdx.x;
    if (idx >= EE * 4) return;
    int e = idx >> 2, q = idx & 3;
    int r = ei[e], c = ei[EE + e];
    const float4* s = (const float4*)(g_xs + (size_t)r * DD + q * 16);
    float4* d = (float4*)(g_agg + (size_t)c * DD + q * 16);
    #pragma unroll
    for (int k = 0; k < 4; ++k) {
        float4 v = s[k];
        asm volatile("red.global.add.v4.f32 [%0], {%1,%2,%3,%4};"
                     :: "l"(d + k), "f"(v.x), "f"(v.y), "f"(v.z), "f"(v.w) : "memory");
    }
}

// step 0: tg0[g][m] += sum over nodes in g of zx[n][m]^2  (batch sorted -> run-length)
__global__ void k_step0(const int* __restrict__ batch) {
    __shared__ int ids[64];
    int tid = threadIdx.x;            // 128 threads, col = tid
    int r0 = blockIdx.x * 64;
    if (tid < 64) { int rg = r0 + tid; ids[tid] = (rg < NN) ? batch[rg] : 0; }
    __syncthreads();
    float s = 0.f;
    int gp = ids[0];
    for (int rr = 0; rr < 64; ++rr) {
        int rg = r0 + rr;
        int g = ids[rr];
        if (g != gp) { atomicAdd(g_tg + gp * HS + tid, s); s = 0.f; gp = g; }
        if (rg < NN) { float v = g_zx[(size_t)rg * HS + tid]; s += v * v; }
    }
    atomicAdd(g_tg + gp * HS + tid, s);
}

// ---------------- main register-tiled GEMM ----------------
// O[n,m] = act( X[n,:K] . W[m,:K] + bias[m] )            (SEG=false)
// tg[g,m] += sum_{n in g} (X.W)[n,m] * zx[n,m]           (SEG=true, M==128)
template<int K, int M, int ACT, bool SEG>
__launch_bounds__(256)
__global__ void k_gemm(const float* __restrict__ X, const float* __restrict__ W,
                       const float* __restrict__ bias, float* __restrict__ O,
                       const float* __restrict__ zx, const int* __restrict__ batch)
{
    constexpr int TN = M / 16;
    static_assert(!SEG || M == 128, "SEG requires M=128");
    __shared__ __align__(16) float smem[4096 + 64 * M];
    float* Xs = smem;            // [64][64]
    float* Wk = smem + 4096;     // [64][M], k-major

    int tid = threadIdx.x;
    int tx = tid & 15, ty = tid >> 4;
    int r0 = blockIdx.x * 64;

    float acc[4][TN];
    #pragma unroll
    for (int i = 0; i < 4; ++i)
        #pragma unroll
        for (int j = 0; j < TN; ++j) acc[i][j] = 0.f;

    for (int k0 = 0; k0 < K; k0 += 64) {
        if (k0) __syncthreads();
        // stage X tile (64 rows x 64 k), zero-fill OOB rows
        #pragma unroll
        for (int p = 0; p < 4; ++p) {
            int lin = p * 256 + tid;
            int rr = lin >> 4, c4 = lin & 15;
            float4 v = make_float4(0.f, 0.f, 0.f, 0.f);
            int rg = r0 + rr;
            if (rg < NN) v = *(const float4*)(X + (size_t)rg * K + k0 + c4 * 4);
            *(float4*)(Xs + rr * 64 + c4 * 4) = v;
        }
        // stage W chunk transposed: Wk[k][m] = W[m][k0+k]
        #pragma unroll
        for (int p = 0; p < M / 16; ++p) {
            int lin = p * 256 + tid;
            int m = lin >> 4, kk4 = lin & 15;
            float4 v = *(const float4*)(W + m * K + k0 + kk4 * 4);
            Wk[(kk4 * 4 + 0) * M + m] = v.x;
            Wk[(kk4 * 4 + 1) * M + m] = v.y;
            Wk[(kk4 * 4 + 2) * M + m] = v.z;
            Wk[(kk4 * 4 + 3) * M + m] = v.w;
        }
        __syncthreads();
        #pragma unroll 8
        for (int k = 0; k < 64; ++k) {
            float xr[4];
            #pragma unroll
            for (int i = 0; i < 4; ++i) xr[i] = Xs[(ty * 4 + i) * 64 + k];
            float wr[TN];
            #pragma unroll
            for (int j4 = 0; j4 < TN / 4; ++j4) {
                float4 wv = *(const float4*)(Wk + k * M + tx * TN + j4 * 4);
                wr[j4 * 4 + 0] = wv.x; wr[j4 * 4 + 1] = wv.y;
                wr[j4 * 4 + 2] = wv.z; wr[j4 * 4 + 3] = wv.w;
            }
            #pragma unroll
            for (int i = 0; i < 4; ++i)
                #pragma unroll
                for (int j = 0; j < TN; ++j)
                    acc[i][j] = fmaf(xr[i], wr[j], acc[i][j]);
        }
    }

    if constexpr (!SEG) {
        float bv[TN];
        #pragma unroll
        for (int j = 0; j < TN; ++j) bv[j] = bias ? bias[tx * TN + j] : 0.f;
        #pragma unroll
        for (int i = 0; i < 4; ++i) {
            int rg = r0 + ty * 4 + i;
            if (rg < NN) {
                #pragma unroll
                for (int j4 = 0; j4 < TN / 4; ++j4) {
                    float4 v;
                    v.x = acc[i][j4 * 4 + 0] + bv[j4 * 4 + 0];
                    v.y = acc[i][j4 * 4 + 1] + bv[j4 * 4 + 1];
                    v.z = acc[i][j4 * 4 + 2] + bv[j4 * 4 + 2];
                    v.w = acc[i][j4 * 4 + 3] + bv[j4 * 4 + 3];
                    if (ACT == 1) {  // sigmoid
                        v.x = 1.f / (1.f + __expf(-v.x));
                        v.y = 1.f / (1.f + __expf(-v.y));
                        v.z = 1.f / (1.f + __expf(-v.z));
                        v.w = 1.f / (1.f + __expf(-v.w));
                    }
                    *(float4*)(O + (size_t)rg * M + tx * TN + j4 * 4) = v;
                }
            }
        }
    } else {
        __syncthreads();                       // done reading Xs/Wk
        float* T  = smem;                      // [64][129] padded
        int* ids  = (int*)(smem + 8320);       // within smem budget
        if (tid < 64) { int rg = r0 + tid; ids[tid] = (rg < NN) ? batch[rg] : 0; }
        #pragma unroll
        for (int i = 0; i < 4; ++i) {
            int rr = ty * 4 + i, rg = r0 + rr;
            #pragma unroll
            for (int j = 0; j < TN; ++j) {
                float zv = (rg < NN) ? zx[(size_t)rg * HS + tx * TN + j] : 0.f;
                T[rr * 129 + tx * TN + j] = acc[i][j] * zv;
            }
        }
        __syncthreads();
        if (tid < 128) {                       // batch is sorted: run-length reduce
            float s = 0.f;
            int gp = ids[0];
            for (int rr = 0; rr < 64; ++rr) {
                int g = ids[rr];
                if (g != gp) { atomicAdd(O + gp * HS + tid, s); s = 0.f; gp = g; }
                s += T[rr * 129 + tid];
            }
            atomicAdd(O + gp * HS + tid, s);
        }
    }
}

// ---------------- BN statistics per output column (384 columns, 512 rows) ----------------
__global__ void k_bnstats(const float* __restrict__ gamma, const float* __restrict__ beta) {
    int j = blockIdx.x;
    int i = j >> 7, c = j & 127, h = c & 15, gg = c >> 4;
    int t = threadIdx.x;   // 128
    float s = 0.f, s2 = 0.f;
    for (int r = t; r < 512; r += 128) {
        int sd = r >> 6;
        int g = ((r & 63) << 3) | gg;
        float v = g_tg[i * (GG * HS) + g * HS + (h << 3) + sd];
        s += v; s2 += v * v;
    }
    #pragma unroll
    for (int o = 16; o; o >>= 1) {
        s  += __shfl_down_sync(0xffffffffu, s,  o);
        s2 += __shfl_down_sync(0xffffffffu, s2, o);
    }
    __shared__ float rs[4], rs2[4];
    int w = t >> 5;
    if ((t & 31) == 0) { rs[w] = s; rs2[w] = s2; }
    __syncthreads();
    if (t == 0) {
        float S  = rs[0] + rs[1] + rs[2] + rs[3];
        float S2 = rs2[0] + rs2[1] + rs2[2] + rs2[3];
        float mean = S * (1.f / 512.f);
        float var  = S2 * (1.f / 512.f) - mean * mean;
        float inv  = rsqrtf(var + 1e-5f);
        float sc   = gamma[j] * inv;
        g_bna[j] = sc;
        g_bnb[j] = beta[j] - mean * sc;
    }
}

// ---------------- BN apply + fc1 + relu + fc2 + log_softmax, one block per row ----------------
__global__ void k_mlp(const float* __restrict__ w1, const float* __restrict__ b1,
                      const float* __restrict__ w2, const float* __restrict__ b2,
                      float* __restrict__ out)
{
    int r = blockIdx.x, t = threadIdx.x;   // 128 threads
    __shared__ __align__(16) float v[FOUT];
    __shared__ __align__(16) float u[PEN];
    __shared__ float o10[CC];
    int sd = r >> 6, gb = (r & 63) << 3;
    for (int j = t; j < FOUT; j += 128) {
        int i = j >> 7, c = j & 127, h = c & 15, gg = c >> 4;
        float val = g_tg[i * (GG * HS) + (gb + gg) * HS + (h << 3) + sd];
        v[j] = val * g_bna[j] + g_bnb[j];
    }
    __syncthreads();
    float acc = b1[t];
    const float4* w1r = (const float4*)(w1 + t * FOUT);
    const float4* v4  = (const float4*)v;
    #pragma unroll 8
    for (int j = 0; j < FOUT / 4; ++j) {
        float4 a = w1r[j], bb = v4[j];
        acc += a.x * bb.x + a.y * bb.y + a.z * bb.z + a.w * bb.w;
    }
    u[t] = fmaxf(acc, 0.f);
    __syncthreads();
    if (t < CC) {
        float a2 = b2[t];
        const float4* w2r = (const float4*)(w2 + t * PEN);
        const float4* u4  = (const float4*)u;
        #pragma unroll
        for (int j = 0; j < PEN / 4; ++j) {
            float4 a = w2r[j], bb = u4[j];
            a2 += a.x * bb.x + a.y * bb.y + a.z * bb.z + a.w * bb.w;
        }
        o10[t] = a2;
    }
    __syncthreads();
    if (t == 0) {
        float m = o10[0];
        #pragma unroll
        for (int k = 1; k < CC; ++k) m = fmaxf(m, o10[k]);
        float se = 0.f;
        #pragma unroll
        for (int k = 0; k < CC; ++k) se += expf(o10[k] - m);
        float l = logf(se) + m;
        #pragma unroll
        for (int k = 0; k < CC; ++k) out[r * CC + k] = o10[k] - l;
    }
}

// ---------------- host launcher (graph-capturable: kernels only) ----------------
extern "C" void kernel_launch(void* const* d_in, const int* in_sizes, int n_in,
                              void* d_out, int out_size)
{
    const float* x     = (const float*)d_in[0];
    const int*   ei    = (const int*)  d_in[1];
    const int*   batch = (const int*)  d_in[2];
    const float* adj   = (const float*)d_in[3];
    const float* fh    = (const float*)d_in[4];   // Z0 [H,S,D] = [128][64]
    const float* fcw   = (const float*)d_in[5];
    const float* fcb   = (const float*)d_in[6];
    const float* rww   = (const float*)d_in[7];   // [2][64][64]
    const float* rwb   = (const float*)d_in[8];   // [2][64]
    const float* gamma = (const float*)d_in[9];
    const float* beta  = (const float*)d_in[10];
    const float* w1    = (const float*)d_in[11];
    const float* b1    = (const float*)d_in[12];
    const float* w2    = (const float*)d_in[13];
    const float* b2    = (const float*)d_in[14];
    float* out = (float*)d_out;

    float *p_xh, *p_zx, *p_cur, *p_agg, *p_Z1, *p_Z2, *p_tg;
    cudaGetSymbolAddress((void**)&p_xh,  g_xh);
    cudaGetSymbolAddress((void**)&p_zx,  g_zx);
    cudaGetSymbolAddress((void**)&p_cur, g_cur);
    cudaGetSymbolAddress((void**)&p_agg, g_agg);
    cudaGetSymbolAddress((void**)&p_Z1,  g_Z1);
    cudaGetSymbolAddress((void**)&p_Z2,  g_Z2);
    cudaGetSymbolAddress((void**)&p_tg,  g_tg);

    constexpr int NB = (NN + 63) / 64;   // 1563

    k_zero<<<768, 256>>>();
    k_prep<<<1, 256>>>(adj, fh);
    // xh = sigmoid(x @ fc_w^T + fc_b)
    k_gemm<IND, DD, 1, false><<<NB, 256>>>(x, fcw, fcb, p_xh, nullptr, nullptr);
    // degree + dinv (self-loop included)
    k_deg <<<(EE + 255) / 256, 256>>>(ei);
    k_dinv<<<(NN + 255) / 256, 256>>>();
    // zx = xh @ Z0^T
    k_gemm<DD, HS, 0, false><<<NB, 256>>>(p_xh, fh, nullptr, p_zx, nullptr, nullptr);
    // step 0: tg0 += zx*zx segment-reduced (cheap squared reduce, no GEMM recompute)
    k_step0<<<NB, 128>>>(batch);
    // conv 1
    k_scale  <<<(NN * 16 + 255) / 256, 256>>>(p_xh);
    k_scatter<<<(EE * 4 + 255) / 256, 256>>>(ei);
    k_gemm<DD, DD, 0, false><<<NB, 256>>>(p_agg, rww, rwb, p_cur, nullptr, nullptr);
    // step 1
    k_gemm<DD, HS, 0, true><<<NB, 256>>>(p_cur, p_Z1, nullptr, p_tg + GG * HS, p_zx, batch);
    // conv 2
    k_scale  <<<(NN * 16 + 255) / 256, 256>>>(p_cur);
    k_scatter<<<(EE * 4 + 255) / 256, 256>>>(ei);
    k_gemm<DD, DD, 0, false><<<NB, 256>>>(p_agg, rww + DD * DD, rwb + DD, p_cur, nullptr, nullptr);
    // step 2
    k_gemm<DD, HS, 0, true><<<NB, 256>>>(p_cur, p_Z2, nullptr, p_tg + 2 * GG * HS, p_zx, batch);
    // BN stats + head
    k_bnstats<<<FOUT, 128>>>(gamma, beta);
    k_mlp<<<GG, 128>>>(w1, b1, w2, b2, out);
}

// round 7
// speedup vs baseline: 1.2526x; 1.2526x over previous
#include <cuda_runtime.h>
#include <math.h>

// ---------------- static problem config ----------------
constexpr int NN   = 100000;   // nodes
constexpr int EE   = 1600000;  // edges
constexpr int IND  = 128;      // input dim
constexpr int DD   = 64;       // hidden dim
constexpr int HH   = 16;       // heads
constexpr int GG   = 512;      // graphs
constexpr int HS   = 128;      // H*S
constexpr int FOUT = 384;      // 3*H*S
constexpr int PEN  = 128;
constexpr int CC   = 10;
constexpr int NSB  = (NN + 1023) / 1024;   // scan blocks = 98

// ---------------- device scratch ----------------
__device__ float g_xh [NN * DD];
__device__ float g_zx [NN * HS];
__device__ float g_xs [NN * DD];     // scaled source (dinv[n]*feat[n])
__device__ float g_agg[NN * DD];
__device__ float g_cur[NN * DD];
__device__ float g_dinv[NN];         // out-degree accum -> 1/(deg+1)
__device__ int   g_cnt [NN];         // in-degree (CSR)
__device__ int   g_off [NN + 1];     // CSR offsets
__device__ int   g_woff[NN];         // fill cursors
__device__ int   g_csr [EE];         // source node per in-edge
__device__ int   g_bsum[NSB];
__device__ int   g_bbase[NSB];
__device__ float g_Z1 [HS * DD];
__device__ float g_Z2 [HS * DD];
__device__ float g_tg [3 * GG * HS];
__device__ float g_bna[FOUT];
__device__ float g_bnb[FOUT];

// triu_indices(8,1) row-major
__constant__ int c_iu[28] = {0,0,0,0,0,0,0, 1,1,1,1,1,1, 2,2,2,2,2, 3,3,3,3, 4,4,4, 5,5, 6};
__constant__ int c_ju[28] = {1,2,3,4,5,6,7, 2,3,4,5,6,7, 3,4,5,6,7, 4,5,6,7, 5,6,7, 6,7, 7};

// ---------------- small kernels ----------------
__global__ void k_zero() {
    int i = blockIdx.x * 256 + threadIdx.x;   // 768*256 = 196608 covers all
    if (i < NN) { g_dinv[i] = 0.f; g_cnt[i] = 0; }
    if (i < 3 * GG * HS) g_tg[i] = 0.f;
}

// out-degree (over row) for dinv, in-degree (over col) for CSR
__global__ void k_deg2(const int* __restrict__ ei) {
    int e = blockIdx.x * 256 + threadIdx.x;
    if (e < EE) {
        atomicAdd(&g_dinv[ei[e]], 1.0f);
        atomicAdd(&g_cnt[ei[EE + e]], 1);
    }
}

// per-block exclusive scan of g_cnt (1024/block)
__global__ void k_scan1() {
    __shared__ int sh[1024];
    int i = blockIdx.x * 1024 + threadIdx.x;
    int v = (i < NN) ? g_cnt[i] : 0;
    sh[threadIdx.x] = v;
    __syncthreads();
    for (int o = 1; o < 1024; o <<= 1) {
        int t = (threadIdx.x >= o) ? sh[threadIdx.x - o] : 0;
        __syncthreads();
        sh[threadIdx.x] += t;
        __syncthreads();
    }
    if (i < NN) g_off[i] = sh[threadIdx.x] - v;
    if (threadIdx.x == 1023) g_bsum[blockIdx.x] = sh[1023];
}

__global__ void k_scan2() {
    if (threadIdx.x == 0) {
        int s = 0;
        for (int b = 0; b < NSB; ++b) { g_bbase[b] = s; s += g_bsum[b]; }
    }
}

// finalize offsets + compute dinv (fused elementwise pass)
__global__ void k_scan3() {
    int i = blockIdx.x * 256 + threadIdx.x;
    if (i < NN) {
        int v = g_off[i] + g_bbase[i >> 10];
        g_off[i] = v;
        g_woff[i] = v;
        g_dinv[i] = 1.0f / (g_dinv[i] + 1.0f);   // +1 self loop
    }
    if (i == 0) g_off[NN] = EE;
}

__global__ void k_fill(const int* __restrict__ ei) {
    int e = blockIdx.x * 256 + threadIdx.x;
    if (e < EE) {
        int r = ei[e], c = ei[EE + e];
        int p = atomicAdd(&g_woff[c], 1);
        g_csr[p] = r;
    }
}

// build A, Z1 = A@Z0, Z2 = A@Z1 (one block)
__global__ void k_prep(const float* __restrict__ adj, const float* __restrict__ Z0) {
    __shared__ float A[HH * 64];
    __shared__ float Z1s[HS * DD];
    int t = threadIdx.x;
    for (int p = t; p < HH * 64; p += 256) A[p] = 0.f;
    __syncthreads();
    for (int p = t; p < HH * 28; p += 256) {
        int h = p / 28, q = p % 28;
        float v = fmaxf(adj[h * 28 + q], 0.f);
        A[h * 64 + c_iu[q] * 8 + c_ju[q]] = v;
        A[h * 64 + c_ju[q] * 8 + c_iu[q]] = v;
    }
    __syncthreads();
    for (int p = t; p < HS * DD; p += 256) {
        int h = p >> 9, rem = p & 511, a = rem >> 6, d = rem & 63;
        float s = 0.f;
        #pragma unroll
        for (int b = 0; b < 8; ++b) s += A[h * 64 + a * 8 + b] * Z0[(h * 8 + b) * DD + d];
        Z1s[p] = s; g_Z1[p] = s;
    }
    __syncthreads();
    for (int p = t; p < HS * DD; p += 256) {
        int h = p >> 9, rem = p & 511, a = rem >> 6, d = rem & 63;
        float s = 0.f;
        #pragma unroll
        for (int b = 0; b < 8; ++b) s += A[h * 64 + a * 8 + b] * Z1s[(h * 8 + b) * DD + d];
        g_Z2[p] = s;
    }
}

// warp-per-node gather: agg[n] = xs[n] + sum_{r in in(n)} xs[r]
__global__ __launch_bounds__(256) void k_gather() {
    int n = (blockIdx.x * 256 + threadIdx.x) >> 5;
    int lane = threadIdx.x & 31;
    if (n >= NN) return;
    int s = g_off[n], e2 = g_off[n + 1];
    float2 acc = ((const float2*)g_xs)[(size_t)n * 32 + lane];
    for (int i = s; i < e2; i += 32) {
        int cnt = e2 - i; if (cnt > 32) cnt = 32;
        int idx = (lane < cnt) ? g_csr[i + lane] : 0;
        for (int j = 0; j < cnt; ++j) {
            int r = __shfl_sync(0xffffffffu, idx, j);
            float2 v = ((const float2*)g_xs)[(size_t)r * 32 + lane];
            acc.x += v.x; acc.y += v.y;
        }
    }
    ((float2*)g_agg)[(size_t)n * 32 + lane] = acc;
}

// ---------------- main register-tiled GEMM ----------------
// MODE 0: O = act(X.W^T + b)
// MODE 1: store O and g_xs = O * dinv[row]
// MODE 2: store O and tg(O2) += segreduce(O^2)     (M==128)
// MODE 3: no store; tg(O2) += segreduce((X.W^T) * g_zx)   (M==128)
template<int K, int M, int ACT, int MODE>
__launch_bounds__(256)
__global__ void k_gemm(const float* __restrict__ X, const float* __restrict__ W,
                       const float* __restrict__ bias, float* __restrict__ O,
                       float* __restrict__ O2, const int* __restrict__ batch)
{
    constexpr int TN = M / 16;
    static_assert(MODE < 2 || M == 128, "seg modes require M=128");
    __shared__ __align__(16) float smem[4096 + 64 * M];
    float* Xs = smem;            // [64][64]
    float* Wk = smem + 4096;     // [64][M] k-major

    int tid = threadIdx.x;
    int tx = tid & 15, ty = tid >> 4;
    int r0 = blockIdx.x * 64;

    float acc[4][TN];
    #pragma unroll
    for (int i = 0; i < 4; ++i)
        #pragma unroll
        for (int j = 0; j < TN; ++j) acc[i][j] = 0.f;

    for (int k0 = 0; k0 < K; k0 += 64) {
        if (k0) __syncthreads();
        #pragma unroll
        for (int p = 0; p < 4; ++p) {
            int lin = p * 256 + tid;
            int rr = lin >> 4, c4 = lin & 15;
            float4 v = make_float4(0.f, 0.f, 0.f, 0.f);
            int rg = r0 + rr;
            if (rg < NN) v = *(const float4*)(X + (size_t)rg * K + k0 + c4 * 4);
            *(float4*)(Xs + rr * 64 + c4 * 4) = v;
        }
        #pragma unroll
        for (int p = 0; p < M / 16; ++p) {
            int lin = p * 256 + tid;
            int m = lin >> 4, kk4 = lin & 15;
            float4 v = *(const float4*)(W + m * K + k0 + kk4 * 4);
            Wk[(kk4 * 4 + 0) * M + m] = v.x;
            Wk[(kk4 * 4 + 1) * M + m] = v.y;
            Wk[(kk4 * 4 + 2) * M + m] = v.z;
            Wk[(kk4 * 4 + 3) * M + m] = v.w;
        }
        __syncthreads();
        #pragma unroll 8
        for (int k = 0; k < 64; ++k) {
            float xr[4];
            #pragma unroll
            for (int i = 0; i < 4; ++i) xr[i] = Xs[(ty * 4 + i) * 64 + k];
            float wr[TN];
            #pragma unroll
            for (int j4 = 0; j4 < TN / 4; ++j4) {
                float4 wv = *(const float4*)(Wk + k * M + tx * TN + j4 * 4);
                wr[j4 * 4 + 0] = wv.x; wr[j4 * 4 + 1] = wv.y;
                wr[j4 * 4 + 2] = wv.z; wr[j4 * 4 + 3] = wv.w;
            }
            #pragma unroll
            for (int i = 0; i < 4; ++i)
                #pragma unroll
                for (int j = 0; j < TN; ++j)
                    acc[i][j] = fmaf(xr[i], wr[j], acc[i][j]);
        }
    }

    if constexpr (MODE <= 2) {
        float bv[TN];
        #pragma unroll
        for (int j = 0; j < TN; ++j) bv[j] = bias ? bias[tx * TN + j] : 0.f;
        #pragma unroll
        for (int i = 0; i < 4; ++i) {
            int rg = r0 + ty * 4 + i;
            if (rg < NN) {
                float dv = (MODE == 1) ? g_dinv[rg] : 0.f;
                #pragma unroll
                for (int j4 = 0; j4 < TN / 4; ++j4) {
                    float4 v;
                    v.x = acc[i][j4 * 4 + 0] + bv[j4 * 4 + 0];
                    v.y = acc[i][j4 * 4 + 1] + bv[j4 * 4 + 1];
                    v.z = acc[i][j4 * 4 + 2] + bv[j4 * 4 + 2];
                    v.w = acc[i][j4 * 4 + 3] + bv[j4 * 4 + 3];
                    if (ACT == 1) {
                        v.x = 1.f / (1.f + __expf(-v.x));
                        v.y = 1.f / (1.f + __expf(-v.y));
                        v.z = 1.f / (1.f + __expf(-v.z));
                        v.w = 1.f / (1.f + __expf(-v.w));
                    }
                    // keep activated value in acc for MODE 2 seg
                    acc[i][j4 * 4 + 0] = v.x; acc[i][j4 * 4 + 1] = v.y;
                    acc[i][j4 * 4 + 2] = v.z; acc[i][j4 * 4 + 3] = v.w;
                    *(float4*)(O + (size_t)rg * M + tx * TN + j4 * 4) = v;
                    if (MODE == 1) {
                        float4 w2 = make_float4(v.x * dv, v.y * dv, v.z * dv, v.w * dv);
                        *(float4*)(g_xs + (size_t)rg * M + tx * TN + j4 * 4) = w2;
                    }
                }
            }
        }
    }

    if constexpr (MODE >= 2) {
        __syncthreads();
        float* T  = smem;                      // [64][129]
        int* ids  = (int*)(smem + 8320);
        if (tid < 64) { int rg = r0 + tid; ids[tid] = (rg < NN) ? batch[rg] : 0; }
        #pragma unroll
        for (int i = 0; i < 4; ++i) {
            int rr = ty * 4 + i, rg = r0 + rr;
            #pragma unroll
            for (int j = 0; j < TN; ++j) {
                float prod;
                if (MODE == 2) {
                    prod = (rg < NN) ? acc[i][j] * acc[i][j] : 0.f;
                } else {
                    float zv = (rg < NN) ? g_zx[(size_t)rg * HS + tx * TN + j] : 0.f;
                    prod = acc[i][j] * zv;
                }
                T[rr * 129 + tx * TN + j] = prod;
            }
        }
        __syncthreads();
        if (tid < 128) {
            float s = 0.f;
            int gp = ids[0];
            for (int rr = 0; rr < 64; ++rr) {
                int g = ids[rr];
                if (g != gp) { atomicAdd(O2 + gp * HS + tid, s); s = 0.f; gp = g; }
                s += T[rr * 129 + tid];
            }
            atomicAdd(O2 + gp * HS + tid, s);
        }
    }
}

// ---------------- BN statistics ----------------
__global__ void k_bnstats(const float* __restrict__ gamma, const float* __restrict__ beta) {
    int j = blockIdx.x;
    int i = j >> 7, c = j & 127, h = c & 15, gg = c >> 4;
    int t = threadIdx.x;
    float s = 0.f, s2 = 0.f;
    for (int r = t; r < 512; r += 128) {
        int sd = r >> 6;
        int g = ((r & 63) << 3) | gg;
        float v = g_tg[i * (GG * HS) + g * HS + (h << 3) + sd];
        s += v; s2 += v * v;
    }
    #pragma unroll
    for (int o = 16; o; o >>= 1) {
        s  += __shfl_down_sync(0xffffffffu, s,  o);
        s2 += __shfl_down_sync(0xffffffffu, s2, o);
    }
    __shared__ float rs[4], rs2[4];
    int w = t >> 5;
    if ((t & 31) == 0) { rs[w] = s; rs2[w] = s2; }
    __syncthreads();
    if (t == 0) {
        float S  = rs[0] + rs[1] + rs[2] + rs[3];
        float S2 = rs2[0] + rs2[1] + rs2[2] + rs2[3];
        float mean = S * (1.f / 512.f);
        float var  = S2 * (1.f / 512.f) - mean * mean;
        float inv  = rsqrtf(var + 1e-5f);
        float sc   = gamma[j] * inv;
        g_bna[j] = sc;
        g_bnb[j] = beta[j] - mean * sc;
    }
}

// ---------------- BN apply + fc1 + relu + fc2 + log_softmax ----------------
__global__ void k_mlp(const float* __restrict__ w1, const float* __restrict__ b1,
                      const float* __restrict__ w2, const float* __restrict__ b2,
                      float* __restrict__ out)
{
    int r = blockIdx.x, t = threadIdx.x;
    __shared__ __align__(16) float v[FOUT];
    __shared__ __align__(16) float u[PEN];
    __shared__ float o10[CC];
    int sd = r >> 6, gb = (r & 63) << 3;
    for (int j = t; j < FOUT; j += 128) {
        int i = j >> 7, c = j & 127, h = c & 15, gg = c >> 4;
        float val = g_tg[i * (GG * HS) + (gb + gg) * HS + (h << 3) + sd];
        v[j] = val * g_bna[j] + g_bnb[j];
    }
    __syncthreads();
    float acc = b1[t];
    const float4* w1r = (const float4*)(w1 + t * FOUT);
    const float4* v4  = (const float4*)v;
    #pragma unroll 8
    for (int j = 0; j < FOUT / 4; ++j) {
        float4 a = w1r[j], bb = v4[j];
        acc += a.x * bb.x + a.y * bb.y + a.z * bb.z + a.w * bb.w;
    }
    u[t] = fmaxf(acc, 0.f);
    __syncthreads();
    if (t < CC) {
        float a2 = b2[t];
        const float4* w2r = (const float4*)(w2 + t * PEN);
        const float4* u4  = (const float4*)u;
        #pragma unroll
        for (int j = 0; j < PEN / 4; ++j) {
            float4 a = w2r[j], bb = u4[j];
            a2 += a.x * bb.x + a.y * bb.y + a.z * bb.z + a.w * bb.w;
        }
        o10[t] = a2;
    }
    __syncthreads();
    if (t == 0) {
        float m = o10[0];
        #pragma unroll
        for (int k = 1; k < CC; ++k) m = fmaxf(m, o10[k]);
        float se = 0.f;
        #pragma unroll
        for (int k = 0; k < CC; ++k) se += expf(o10[k] - m);
        float l = logf(se) + m;
        #pragma unroll
        for (int k = 0; k < CC; ++k) out[r * CC + k] = o10[k] - l;
    }
}

// ---------------- host launcher ----------------
extern "C" void kernel_launch(void* const* d_in, const int* in_sizes, int n_in,
                              void* d_out, int out_size)
{
    const float* x     = (const float*)d_in[0];
    const int*   ei    = (const int*)  d_in[1];
    const int*   batch = (const int*)  d_in[2];
    const float* adj   = (const float*)d_in[3];
    const float* fh    = (const float*)d_in[4];
    const float* fcw   = (const float*)d_in[5];
    const float* fcb   = (const float*)d_in[6];
    const float* rww   = (const float*)d_in[7];
    const float* rwb   = (const float*)d_in[8];
    const float* gamma = (const float*)d_in[9];
    const float* beta  = (const float*)d_in[10];
    const float* w1    = (const float*)d_in[11];
    const float* b1    = (const float*)d_in[12];
    const float* w2    = (const float*)d_in[13];
    const float* b2    = (const float*)d_in[14];
    float* out = (float*)d_out;

    float *p_xh, *p_zx, *p_cur, *p_agg, *p_tg, *p_Z1, *p_Z2;
    cudaGetSymbolAddress((void**)&p_xh,  g_xh);
    cudaGetSymbolAddress((void**)&p_zx,  g_zx);
    cudaGetSymbolAddress((void**)&p_cur, g_cur);
    cudaGetSymbolAddress((void**)&p_agg, g_agg);
    cudaGetSymbolAddress((void**)&p_Z1,  g_Z1);
    cudaGetSymbolAddress((void**)&p_Z2,  g_Z2);
    cudaGetSymbolAddress((void**)&p_tg,  g_tg);

    constexpr int NB = (NN + 63) / 64;   // 1563

    k_zero<<<768, 256>>>();
    k_prep<<<1, 256>>>(adj, fh);
    k_deg2<<<(EE + 255) / 256, 256>>>(ei);
    // CSR build (+dinv fused into scan3)
    k_scan1<<<NSB, 1024>>>();
    k_scan2<<<1, 32>>>();
    k_scan3<<<(NN + 255) / 256, 256>>>();
    k_fill<<<(EE + 255) / 256, 256>>>(ei);
    // xh = sigmoid(x@fcw^T+b); xs = xh*dinv
    k_gemm<IND, DD, 1, 1><<<NB, 256>>>(x, fcw, fcb, p_xh, nullptr, nullptr);
    // zx = xh@Z0^T ; tg0 += seg(zx^2)
    k_gemm<DD, HS, 0, 2><<<NB, 256>>>(p_xh, fh, nullptr, p_zx, p_tg, batch);
    // conv 1: gather, linear (writes cur and xs=cur*dinv)
    k_gather<<<(NN * 32 + 255) / 256, 256>>>();
    k_gemm<DD, DD, 0, 1><<<NB, 256>>>(p_agg, rww, rwb, p_cur, nullptr, nullptr);
    // step 1
    k_gemm<DD, HS, 0, 3><<<NB, 256>>>(p_cur, p_Z1, nullptr, nullptr, p_tg + GG * HS, batch);
    // conv 2: gather, linear (plain store)
    k_gather<<<(NN * 32 + 255) / 256, 256>>>();
    k_gemm<DD, DD, 0, 0><<<NB, 256>>>(p_agg, rww + DD * DD, rwb + DD, p_cur, nullptr, nullptr);
    // step 2
    k_gemm<DD, HS, 0, 3><<<NB, 256>>>(p_cur, p_Z2, nullptr, nullptr, p_tg + 2 * GG * HS, batch);
    // head
    k_bnstats<<<FOUT, 128>>>(gamma, beta);
    k_mlp<<<GG, 128>>>(w1, b1, w2, b2, out);
}